// round 6
// baseline (speedup 1.0000x reference)
#include <cuda_runtime.h>
#include <cuda_fp16.h>

// RC backward-Euler scan. v6:
//  - coefficients 8 B/step: b (fp32) + (h,g) packed __half2, transposed planes
//  - S=128, warm-up = 4 chunks (512 steps)
//  - scan: flat 40-block (5 seg x 8 blk) software pipeline, prefetch depth 3
//    (48 steps ~ 620 cyc: covers DRAM-cold 577-cyc loads)
//  - L2 evict_last policy on coeff stores (pre) and loads (scan)
//  - evict-first output stores

#define DT_S   1800.0f
#define GA     31.388f
#define S2     128
#define PWARM  4
#define NBLK   ((PWARM + 1) * (S2 / 16))     // 40
#define NMAX   (1 << 22)

static __device__ float4 g_b4[NMAX / 4];    // 4 steps of b per entry
static __device__ uint4  g_hg4[NMAX / 4];   // 4 steps of packed (h,g) per entry

struct DCst {
    float iRie, iRea, invCin, invCen;
    float M11, nM12, nM21;
    float kD, kE, k0a, k1a;
    float gam, del, c_h, c_g1, dtCen;
};

__device__ __forceinline__ DCst make_consts(float R_ie, float R_ea,
                                            float C_in, float C_en)
{
    DCst c;
    c.iRie   = 1.0f / R_ie;
    c.iRea   = 1.0f / R_ea;
    c.invCin = 1.0f / C_in;
    c.invCen = 1.0f / C_en;
    c.M11  = 1.0f + DT_S * (c.iRea + c.iRie) * c.invCen;
    c.nM12 = DT_S * c.iRie * c.invCen;
    c.nM21 = DT_S * c.iRie * c.invCin;
    c.kD   = c.M11  / c.nM12;
    c.kE   = c.nM21 / c.nM12;
    c.k0a  = 1.0f / c.M11;
    c.k1a  = c.nM21 / c.M11;
    float alpha = 1.0f + DT_S * c.iRie * c.invCin;   // M22 = alpha + beta*u
    float beta  = DT_S * c.invCin;
    c.gam  = c.M11 * alpha - c.nM12 * c.nM21;        // det = gam + del*u
    c.del  = c.M11 * beta;
    c.c_h  = c.nM12 * DT_S * c.invCin;
    c.c_g1 = c.M11  * DT_S * c.invCin;
    c.dtCen = DT_S * c.invCen;
    return c;
}

__device__ __forceinline__ float frcp_approx(float x) {
    float r;
    asm("rcp.approx.f32 %0, %1;" : "=f"(r) : "f"(x));
    return r;
}

// -------- L2 evict_last cache-policy helpers ------------------------------
__device__ __forceinline__ unsigned long long mk_policy_el() {
    unsigned long long p;
    asm("createpolicy.fractional.L2::evict_last.b64 %0, 1.0;" : "=l"(p));
    return p;
}
__device__ __forceinline__ void st_el_f4(float4* p, float4 v, unsigned long long pol) {
    asm volatile("st.global.L2::cache_hint.v4.f32 [%0], {%1,%2,%3,%4}, %5;"
        :: "l"(p), "f"(v.x), "f"(v.y), "f"(v.z), "f"(v.w), "l"(pol) : "memory");
}
__device__ __forceinline__ void st_el_u4(uint4* p, uint4 v, unsigned long long pol) {
    asm volatile("st.global.L2::cache_hint.v4.b32 [%0], {%1,%2,%3,%4}, %5;"
        :: "l"(p), "r"(v.x), "r"(v.y), "r"(v.z), "r"(v.w), "l"(pol) : "memory");
}
__device__ __forceinline__ float4 ld_el_f4(const float4* p, unsigned long long pol) {
    float4 v;
    asm volatile("ld.global.nc.L2::cache_hint.v4.f32 {%0,%1,%2,%3}, [%4], %5;"
        : "=f"(v.x), "=f"(v.y), "=f"(v.z), "=f"(v.w) : "l"(p), "l"(pol));
    return v;
}
__device__ __forceinline__ uint4 ld_el_u4(const uint4* p, unsigned long long pol) {
    uint4 v;
    asm volatile("ld.global.nc.L2::cache_hint.v4.b32 {%0,%1,%2,%3}, [%4], %5;"
        : "=r"(v.x), "=r"(v.y), "=r"(v.z), "=r"(v.w) : "l"(p), "l"(pol));
    return v;
}

// ------------------------------------------- pre-pass: compute + transpose
__global__ void __launch_bounds__(256)
pre_t_kernel(const float* __restrict__ To,  const float* __restrict__ Irr,
             const float* __restrict__ Qint, const float* __restrict__ Qah,
             const float* __restrict__ Ria,
             const float* pR_ie, const float* pR_ea,
             const float* pC_in, const float* pC_en,
             const float* pA_si, const float* pA_se,
             const float* pA_ii, const float* pA_ie,
             int C)
{
    __shared__ float4 tb[8][33];
    __shared__ uint4  th[8][33];

    const DCst c = make_consts(__ldg(pR_ie), __ldg(pR_ea), __ldg(pC_in), __ldg(pC_en));
    float a_si = __ldg(pA_si), a_se = __ldg(pA_se);
    float a_ii = __ldg(pA_ii), a_ie = __ldg(pA_ie);

    int j0 = blockIdx.x * 32;
    int k0 = blockIdx.y * 32;

    {   // phase 1: coalesced read + compute
        int kg = threadIdx.x & 7;        // 0..7 (x4 steps)
        int jj = threadIdx.x >> 3;       // 0..31
        int t  = (j0 + jj) * S2 + k0 + 4 * kg;

        float4 to4 = *(const float4*)(To  + t);
        float4 ir4 = *(const float4*)(Irr + t);
        float4 qi4 = *(const float4*)(Qint + t);
        float4 qa4 = *(const float4*)(Qah + t);
        float4 ra4 = *(const float4*)(Ria + t);
        const float* to = (const float*)&to4;
        const float* ir = (const float*)&ir4;
        const float* qi = (const float*)&qi4;
        const float* qa = (const float*)&qa4;
        const float* ra = (const float*)&ra4;

        float Rc[4], P[4], ipv[4];
        #pragma unroll
        for (int i = 0; i < 4; ++i) {
            Rc[i] = fmaxf(ra[i], 1e-4f);
            P[i]  = fmaf(c.gam, Rc[i], c.del);
        }
        float p01 = P[0] * P[1], p23 = P[2] * P[3];
        float ipa = frcp_approx(p01 * p23);
        float i01 = ipa * p23, i23 = ipa * p01;
        ipv[0] = i01 * P[1]; ipv[1] = i01 * P[0];
        ipv[2] = i23 * P[3]; ipv[3] = i23 * P[2];
        #pragma unroll
        for (int i = 0; i < 4; ++i)      // one Newton polish
            ipv[i] = ipv[i] * fmaf(-P[i], ipv[i], 2.0f);

        float4 b4;  float* bp = (float*)&b4;
        uint4  hg4; unsigned* hp = (unsigned*)&hg4;
        #pragma unroll
        for (int i = 0; i < 4; ++i) {
            float ip  = ipv[i];
            float rp  = Rc[i] * ip;                 // invdet
            float Qs  = GA * fminf(fmaxf(ir[i], 0.0f), 2000.0f);
            float qh  = fmaxf(qa[i], 0.0f);
            float b   = c.nM12 * rp;
            float a   = fmaf(c.k1a, b, c.k0a);
            float s0  = c.dtCen * fmaf(to[i], c.iRea,
                                 fmaf(a_se, Qs, a_ie * qi[i]));
            float s1  = fmaf(a_si, Qs, fmaf(a_ii, qi[i], qh));
            float T1  = ip * fmaf(Rc[i], s1, to[i]);
            float h   = fmaf(c.c_h, T1, a * s0);
            float g   = fmaf(c.c_g1, T1, c.nM21 * (rp * s0));
            bp[i] = b;
            __half2 p = __floats2half2_rn(h, g);
            hp[i] = *reinterpret_cast<unsigned*>(&p);
        }
        tb[kg][jj] = b4;
        th[kg][jj] = hg4;
    }
    __syncthreads();
    {   // phase 2: transposed coalesced 512B writes, L2 evict_last
        unsigned long long pol = mk_policy_el();
        int jj = threadIdx.x & 31;
        int kg = threadIdx.x >> 5;       // 0..7
        int idx = ((k0 >> 2) + kg) * C + j0 + jj;
        st_el_f4(&g_b4[idx],  tb[kg][jj], pol);
        st_el_u4(&g_hg4[idx], th[kg][jj], pol);
    }
}

// ------------------------------------------------------------- scan kernel
struct G16 { float4 b[4]; uint4 hg[4]; };

__device__ __forceinline__ void load_block(G16& d, int m, int colBase, int C,
                                           unsigned long long pol)
{
    int col = colBase + (m >> 3);
    if (col < 0) col = 0;                 // harmless dummy load for warm skips
    int kgBase = (m & 7) * 4;
    #pragma unroll
    for (int i = 0; i < 4; ++i) {
        int idx = (kgBase + i) * C + col;
        d.b[i]  = ld_el_f4(&g_b4[idx],  pol);
        d.hg[i] = ld_el_u4(&g_hg4[idx], pol);
    }
}

__device__ __forceinline__ void process16(
    const G16& d, float& Te, float& Tin,
    float kD, float kE, float k0a, float k1a,
    bool doOut, float* __restrict__ outp)
{
    #pragma unroll
    for (int i = 0; i < 4; ++i) {
        const float*    bb = (const float*)&d.b[i];
        const unsigned* hh = (const unsigned*)&d.hg[i];
        float4 v;
        float* vv = (float*)&v;
        #pragma unroll
        for (int e = 0; e < 4; ++e) {
            float b = bb[e];
            unsigned hgu = hh[e];
            __half2 hg2 = *reinterpret_cast<const __half2*>(&hgu);
            float2 hg = __half22float2(hg2);
            float a  = fmaf(k1a, b, k0a);
            float dd = kD * b;
            float ee = kE * b;
            float p  = fmaf(b,  Tin, hg.x);
            float q  = fmaf(ee, Te,  hg.y);
            float Te_n  = fmaf(a,  Te,  p);
            float Tin_n = fmaf(dd, Tin, q);
            Tin_n = fminf(fmaxf(Tin_n, 5.0f), 45.0f);
            Te = Te_n; Tin = Tin_n;
            vv[e] = Tin;
        }
        if (doOut) __stcs((float4*)(outp + 4 * i), v);
    }
}

__global__ void __launch_bounds__(128)
scan_t_kernel(float* __restrict__ out,
              const float* pR_ie, const float* pR_ea,
              const float* pC_in, const float* pC_en,
              const float* pTin0, int C)
{
    int j = blockIdx.x * 128 + threadIdx.x;
    if (j >= C) return;

    const DCst c = make_consts(__ldg(pR_ie), __ldg(pR_ea), __ldg(pC_in), __ldg(pC_en));
    float kD = c.kD, kE = c.kE, k0a = c.k0a, k1a = c.k1a;
    float Tin0 = __ldg(pTin0);
    unsigned long long pol = mk_policy_el();

    float Te = Tin0, Tin = Tin0;
    int colBase = j - PWARM;
    float* outBase = out + j * S2;

    G16 buf[4];
    load_block(buf[0], 0, colBase, C, pol);
    load_block(buf[1], 1, colBase, C, pol);
    load_block(buf[2], 2, colBase, C, pol);

    #pragma unroll 1
    for (int mm = 0; mm < NBLK; mm += 4) {
        #pragma unroll
        for (int ph = 0; ph < 4; ++ph) {
            int m = mm + ph;
            if (m + 3 < NBLK)
                load_block(buf[(ph + 3) & 3], m + 3, colBase, C, pol);
            int seg = m >> 3;
            if (colBase + seg >= 0) {
                bool doOut = (seg == PWARM);
                process16(buf[ph], Te, Tin, kD, kE, k0a, k1a,
                          doOut, outBase + ((m & 7) * 16));
            }
        }
    }
}

// ------------------------------------------- exact fallback (ragged n only)
__global__ void seq_kernel(const float* __restrict__ To, const float* __restrict__ Irr,
                           const float* __restrict__ Qint, const float* __restrict__ Qah,
                           const float* __restrict__ Ria,
                           const float* pR_ie, const float* pR_ea,
                           const float* pC_in, const float* pC_en,
                           const float* pA_si, const float* pA_se,
                           const float* pA_ii, const float* pA_ie,
                           const float* pTin0,
                           float* __restrict__ out, int n)
{
    float iRie = 1.0f / *pR_ie, iRea = 1.0f / *pR_ea;
    float invCin = 1.0f / *pC_in, invCen = 1.0f / *pC_en;
    float a_si = *pA_si, a_se = *pA_se, a_ii = *pA_ii, a_ie = *pA_ie;
    float M11  = 1.0f + DT_S * (iRea + iRie) * invCen;
    float nM12 = DT_S * iRie * invCen;
    float nM21 = DT_S * iRie * invCin;
    float Te = *pTin0, Tin = *pTin0;
    for (int t = 0; t < n; ++t) {
        float Ria_c = fmaxf(Ria[t], 1e-4f);
        float u     = 1.0f / Ria_c;
        float Qsol  = GA * fminf(fmaxf(Irr[t], 0.0f), 2000.0f);
        float qah   = fmaxf(Qah[t], 0.0f);
        float M22 = 1.0f + DT_S * (u + iRie) * invCin;
        float det = M11 * M22 - nM12 * nM21;
        float invdet = 1.0f / det;
        float b0 = To[t] * iRea * invCen + (a_se * Qsol + a_ie * Qint[t]) * invCen;
        float b1 = (To[t] * u + a_si * Qsol + a_ii * Qint[t] + qah) * invCin;
        float r0 = Te + DT_S * b0;
        float r1 = Tin + DT_S * b1;
        float Te_n  = (M22 * r0 + nM12 * r1) * invdet;
        float Tin_n = (M11 * r1 + nM21 * r0) * invdet;
        Tin_n = fminf(fmaxf(Tin_n, 5.0f), 45.0f);
        Te = Te_n; Tin = Tin_n;
        out[t] = Tin_n;
    }
}

extern "C" void kernel_launch(void* const* d_in, const int* in_sizes, int n_in,
                              void* d_out, int out_size)
{
    const float* pR_ie = (const float*)d_in[0];
    const float* pR_ea = (const float*)d_in[1];
    const float* pC_in = (const float*)d_in[2];
    const float* pC_en = (const float*)d_in[3];
    const float* pA_si = (const float*)d_in[4];
    const float* pA_se = (const float*)d_in[5];
    const float* pA_ii = (const float*)d_in[6];
    const float* pA_ie = (const float*)d_in[7];
    const float* pTin0 = (const float*)d_in[8];
    const float* To   = (const float*)d_in[9];
    const float* Irr  = (const float*)d_in[10];
    const float* Qint = (const float*)d_in[11];
    const float* Qah  = (const float*)d_in[12];
    const float* Ria  = (const float*)d_in[13];
    float* out = (float*)d_out;
    int n = in_sizes[9];

    if (n > NMAX || n <= 0 || (n % S2) != 0 || ((n / S2) % 128) != 0) {
        seq_kernel<<<1, 1>>>(To, Irr, Qint, Qah, Ria,
                             pR_ie, pR_ea, pC_in, pC_en,
                             pA_si, pA_se, pA_ii, pA_ie, pTin0, out, n);
        return;
    }

    int C = n / S2;                          // 32768
    dim3 pgrid(C / 32, S2 / 32);             // (1024, 4) blocks of 256
    pre_t_kernel<<<pgrid, 256>>>(To, Irr, Qint, Qah, Ria,
                                 pR_ie, pR_ea, pC_in, pC_en,
                                 pA_si, pA_se, pA_ii, pA_ie, C);

    scan_t_kernel<<<C / 128, 128>>>(out, pR_ie, pR_ea, pC_in, pC_en, pTin0, C);
}

// round 7
// speedup vs baseline: 1.0802x; 1.0802x over previous
#include <cuda_runtime.h>
#include <cuda_fp16.h>

// RC backward-Euler scan. v7:
//  - coefficients 8 B/step: b (fp32) + (h,g) packed __half2, transposed planes
//  - S=128, warm-up = 3 chunks (384 steps)
//  - scan: TWO independent chunk-chains per thread (j and j+C/2) ->
//    ~1.8 instr/cyc issue demand per warp hides chain+memory latency via ILP
//  - branch-free warm-up: clamped column + carry reset keeps one basic block
//  - 16-step register double-buffer per chain; evict-first output stores

#define DT_S   1800.0f
#define GA     31.388f
#define S2     128
#define PWARM  3
#define NSEG   (PWARM + 1)
#define NMAX   (1 << 22)

static __device__ float4 g_b4[NMAX / 4];    // 4 steps of b per entry
static __device__ uint4  g_hg4[NMAX / 4];   // 4 steps of packed (h,g) per entry

struct DCst {
    float iRie, iRea, invCin, invCen;
    float M11, nM12, nM21;
    float kD, kE, k0a, k1a;
    float gam, del, c_h, c_g1, dtCen;
};

__device__ __forceinline__ DCst make_consts(float R_ie, float R_ea,
                                            float C_in, float C_en)
{
    DCst c;
    c.iRie   = 1.0f / R_ie;
    c.iRea   = 1.0f / R_ea;
    c.invCin = 1.0f / C_in;
    c.invCen = 1.0f / C_en;
    c.M11  = 1.0f + DT_S * (c.iRea + c.iRie) * c.invCen;
    c.nM12 = DT_S * c.iRie * c.invCen;
    c.nM21 = DT_S * c.iRie * c.invCin;
    c.kD   = c.M11  / c.nM12;
    c.kE   = c.nM21 / c.nM12;
    c.k0a  = 1.0f / c.M11;
    c.k1a  = c.nM21 / c.M11;
    float alpha = 1.0f + DT_S * c.iRie * c.invCin;   // M22 = alpha + beta*u
    float beta  = DT_S * c.invCin;
    c.gam  = c.M11 * alpha - c.nM12 * c.nM21;        // det = gam + del*u
    c.del  = c.M11 * beta;
    c.c_h  = c.nM12 * DT_S * c.invCin;
    c.c_g1 = c.M11  * DT_S * c.invCin;
    c.dtCen = DT_S * c.invCen;
    return c;
}

__device__ __forceinline__ float frcp_approx(float x) {
    float r;
    asm("rcp.approx.f32 %0, %1;" : "=f"(r) : "f"(x));
    return r;
}

// ------------------------------------------- pre-pass: compute + transpose
__global__ void __launch_bounds__(256)
pre_t_kernel(const float* __restrict__ To,  const float* __restrict__ Irr,
             const float* __restrict__ Qint, const float* __restrict__ Qah,
             const float* __restrict__ Ria,
             const float* pR_ie, const float* pR_ea,
             const float* pC_in, const float* pC_en,
             const float* pA_si, const float* pA_se,
             const float* pA_ii, const float* pA_ie,
             int C)
{
    __shared__ float4 tb[8][33];
    __shared__ uint4  th[8][33];

    const DCst c = make_consts(__ldg(pR_ie), __ldg(pR_ea), __ldg(pC_in), __ldg(pC_en));
    float a_si = __ldg(pA_si), a_se = __ldg(pA_se);
    float a_ii = __ldg(pA_ii), a_ie = __ldg(pA_ie);

    int j0 = blockIdx.x * 32;
    int k0 = blockIdx.y * 32;

    {   // phase 1: coalesced read + compute
        int kg = threadIdx.x & 7;        // 0..7 (x4 steps)
        int jj = threadIdx.x >> 3;       // 0..31
        int t  = (j0 + jj) * S2 + k0 + 4 * kg;

        float4 to4 = *(const float4*)(To  + t);
        float4 ir4 = *(const float4*)(Irr + t);
        float4 qi4 = *(const float4*)(Qint + t);
        float4 qa4 = *(const float4*)(Qah + t);
        float4 ra4 = *(const float4*)(Ria + t);
        const float* to = (const float*)&to4;
        const float* ir = (const float*)&ir4;
        const float* qi = (const float*)&qi4;
        const float* qa = (const float*)&qa4;
        const float* ra = (const float*)&ra4;

        float Rc[4], P[4], ipv[4];
        #pragma unroll
        for (int i = 0; i < 4; ++i) {
            Rc[i] = fmaxf(ra[i], 1e-4f);
            P[i]  = fmaf(c.gam, Rc[i], c.del);
        }
        float p01 = P[0] * P[1], p23 = P[2] * P[3];
        float ipa = frcp_approx(p01 * p23);
        float i01 = ipa * p23, i23 = ipa * p01;
        ipv[0] = i01 * P[1]; ipv[1] = i01 * P[0];
        ipv[2] = i23 * P[3]; ipv[3] = i23 * P[2];
        #pragma unroll
        for (int i = 0; i < 4; ++i)      // one Newton polish
            ipv[i] = ipv[i] * fmaf(-P[i], ipv[i], 2.0f);

        float4 b4;  float* bp = (float*)&b4;
        uint4  hg4; unsigned* hp = (unsigned*)&hg4;
        #pragma unroll
        for (int i = 0; i < 4; ++i) {
            float ip  = ipv[i];
            float rp  = Rc[i] * ip;                 // invdet
            float Qs  = GA * fminf(fmaxf(ir[i], 0.0f), 2000.0f);
            float qh  = fmaxf(qa[i], 0.0f);
            float b   = c.nM12 * rp;
            float a   = fmaf(c.k1a, b, c.k0a);
            float s0  = c.dtCen * fmaf(to[i], c.iRea,
                                 fmaf(a_se, Qs, a_ie * qi[i]));
            float s1  = fmaf(a_si, Qs, fmaf(a_ii, qi[i], qh));
            float T1  = ip * fmaf(Rc[i], s1, to[i]);
            float h   = fmaf(c.c_h, T1, a * s0);
            float g   = fmaf(c.c_g1, T1, c.nM21 * (rp * s0));
            bp[i] = b;
            __half2 p = __floats2half2_rn(h, g);
            hp[i] = *reinterpret_cast<unsigned*>(&p);
        }
        tb[kg][jj] = b4;
        th[kg][jj] = hg4;
    }
    __syncthreads();
    {   // phase 2: transposed coalesced 512B writes
        int jj = threadIdx.x & 31;
        int kg = threadIdx.x >> 5;       // 0..7
        int idx = ((k0 >> 2) + kg) * C + j0 + jj;
        g_b4[idx]  = tb[kg][jj];
        g_hg4[idx] = th[kg][jj];
    }
}

// ------------------------------------------------------------- scan kernel
struct G16 { float4 b[4]; uint4 hg[4]; };

__device__ __forceinline__ void load16(G16& d, int kgBase, int col, int C) {
    #pragma unroll
    for (int i = 0; i < 4; ++i) {
        int idx = (kgBase + i) * C + col;
        d.b[i]  = __ldg(&g_b4[idx]);
        d.hg[i] = __ldg(&g_hg4[idx]);
    }
}

// One 16-step block for BOTH chains, hand-interleaved for ILP.
__device__ __forceinline__ void dual16(
    const G16& dA, const G16& dB,
    float& TeA, float& TinA, float& TeB, float& TinB,
    float kD, float kE, float k0a, float k1a,
    bool doOut, float* __restrict__ outA, float* __restrict__ outB)
{
    #pragma unroll
    for (int i = 0; i < 4; ++i) {
        const float*    bA = (const float*)&dA.b[i];
        const unsigned* hA = (const unsigned*)&dA.hg[i];
        const float*    bB = (const float*)&dB.b[i];
        const unsigned* hB = (const unsigned*)&dB.hg[i];
        float4 vA, vB;
        float* va = (float*)&vA;
        float* vb = (float*)&vB;
        #pragma unroll
        for (int e = 0; e < 4; ++e) {
            // chain A step
            float ba = bA[e];
            unsigned ua = hA[e];
            float2 hga = __half22float2(*reinterpret_cast<const __half2*>(&ua));
            float aa  = fmaf(k1a, ba, k0a);
            float dda = kD * ba;
            float eea = kE * ba;
            float pa  = fmaf(ba,  TinA, hga.x);
            float qa  = fmaf(eea, TeA,  hga.y);
            // chain B step (independent -> fills A's latency)
            float bb = bB[e];
            unsigned ub = hB[e];
            float2 hgb = __half22float2(*reinterpret_cast<const __half2*>(&ub));
            float ab  = fmaf(k1a, bb, k0a);
            float ddb = kD * bb;
            float eeb = kE * bb;
            float pb  = fmaf(bb,  TinB, hgb.x);
            float qb  = fmaf(eeb, TeB,  hgb.y);
            // commits
            float TeAn  = fmaf(aa,  TeA,  pa);
            float TinAn = fmaf(dda, TinA, qa);
            float TeBn  = fmaf(ab,  TeB,  pb);
            float TinBn = fmaf(ddb, TinB, qb);
            TinAn = fminf(fmaxf(TinAn, 5.0f), 45.0f);
            TinBn = fminf(fmaxf(TinBn, 5.0f), 45.0f);
            TeA = TeAn; TinA = TinAn;
            TeB = TeBn; TinB = TinBn;
            va[e] = TinA;
            vb[e] = TinB;
        }
        if (doOut) {
            __stcs((float4*)(outA + 4 * i), vA);
            __stcs((float4*)(outB + 4 * i), vB);
        }
    }
}

__global__ void __launch_bounds__(128)
scan_t_kernel(float* __restrict__ out,
              const float* pR_ie, const float* pR_ea,
              const float* pC_in, const float* pC_en,
              const float* pTin0, int C)
{
    int tid = blockIdx.x * 128 + threadIdx.x;
    int half = C >> 1;
    if (tid >= half) return;

    const DCst c = make_consts(__ldg(pR_ie), __ldg(pR_ea), __ldg(pC_in), __ldg(pC_en));
    float kD = c.kD, kE = c.kE, k0a = c.k0a, k1a = c.k1a;
    float Tin0 = __ldg(pTin0);

    int jA = tid;            // may need warm-up truncation (jA < PWARM)
    int jB = tid + half;     // always jB >= PWARM
    float TeA = Tin0, TinA = Tin0, TeB = Tin0, TinB = Tin0;
    float* outA = out + jA * S2;
    float* outB = out + jB * S2;

    #pragma unroll 1
    for (int seg = 0; seg < NSEG; ++seg) {
        int colA = jA - PWARM + seg;
        int cA   = colA < 0 ? 0 : colA;     // clamped load; carry reset below
        int cB   = jB - PWARM + seg;
        bool doOut = (seg == PWARM);

        G16 A0, A1, B0, B1;
        load16(A0, 0, cA, C);
        load16(B0, 0, cB, C);

        #pragma unroll 1
        for (int kt = 0; kt < S2; kt += 32) {
            int kg = kt >> 2;
            load16(A1, kg + 4, cA, C);
            load16(B1, kg + 4, cB, C);
            dual16(A0, B0, TeA, TinA, TeB, TinB, kD, kE, k0a, k1a,
                   doOut, outA + kt, outB + kt);
            if (kt + 32 < S2) {
                load16(A0, kg + 8, cA, C);
                load16(B0, kg + 8, cB, C);
            }
            dual16(A1, B1, TeA, TinA, TeB, TinB, kD, kE, k0a, k1a,
                   doOut, outA + kt + 16, outB + kt + 16);
        }
        // chain A processed a dummy (clamped) column: restore exact carry so
        // its first real column (col 0) starts from the true initial state.
        if (colA < 0) { TeA = Tin0; TinA = Tin0; }
    }
}

// ------------------------------------------- exact fallback (ragged n only)
__global__ void seq_kernel(const float* __restrict__ To, const float* __restrict__ Irr,
                           const float* __restrict__ Qint, const float* __restrict__ Qah,
                           const float* __restrict__ Ria,
                           const float* pR_ie, const float* pR_ea,
                           const float* pC_in, const float* pC_en,
                           const float* pA_si, const float* pA_se,
                           const float* pA_ii, const float* pA_ie,
                           const float* pTin0,
                           float* __restrict__ out, int n)
{
    float iRie = 1.0f / *pR_ie, iRea = 1.0f / *pR_ea;
    float invCin = 1.0f / *pC_in, invCen = 1.0f / *pC_en;
    float a_si = *pA_si, a_se = *pA_se, a_ii = *pA_ii, a_ie = *pA_ie;
    float M11  = 1.0f + DT_S * (iRea + iRie) * invCen;
    float nM12 = DT_S * iRie * invCen;
    float nM21 = DT_S * iRie * invCin;
    float Te = *pTin0, Tin = *pTin0;
    for (int t = 0; t < n; ++t) {
        float Ria_c = fmaxf(Ria[t], 1e-4f);
        float u     = 1.0f / Ria_c;
        float Qsol  = GA * fminf(fmaxf(Irr[t], 0.0f), 2000.0f);
        float qah   = fmaxf(Qah[t], 0.0f);
        float M22 = 1.0f + DT_S * (u + iRie) * invCin;
        float det = M11 * M22 - nM12 * nM21;
        float invdet = 1.0f / det;
        float b0 = To[t] * iRea * invCen + (a_se * Qsol + a_ie * Qint[t]) * invCen;
        float b1 = (To[t] * u + a_si * Qsol + a_ii * Qint[t] + qah) * invCin;
        float r0 = Te + DT_S * b0;
        float r1 = Tin + DT_S * b1;
        float Te_n  = (M22 * r0 + nM12 * r1) * invdet;
        float Tin_n = (M11 * r1 + nM21 * r0) * invdet;
        Tin_n = fminf(fmaxf(Tin_n, 5.0f), 45.0f);
        Te = Te_n; Tin = Tin_n;
        out[t] = Tin_n;
    }
}

extern "C" void kernel_launch(void* const* d_in, const int* in_sizes, int n_in,
                              void* d_out, int out_size)
{
    const float* pR_ie = (const float*)d_in[0];
    const float* pR_ea = (const float*)d_in[1];
    const float* pC_in = (const float*)d_in[2];
    const float* pC_en = (const float*)d_in[3];
    const float* pA_si = (const float*)d_in[4];
    const float* pA_se = (const float*)d_in[5];
    const float* pA_ii = (const float*)d_in[6];
    const float* pA_ie = (const float*)d_in[7];
    const float* pTin0 = (const float*)d_in[8];
    const float* To   = (const float*)d_in[9];
    const float* Irr  = (const float*)d_in[10];
    const float* Qint = (const float*)d_in[11];
    const float* Qah  = (const float*)d_in[12];
    const float* Ria  = (const float*)d_in[13];
    float* out = (float*)d_out;
    int n = in_sizes[9];

    int C = n / S2;
    if (n > NMAX || n <= 0 || (n % S2) != 0 || (C % 256) != 0) {
        seq_kernel<<<1, 1>>>(To, Irr, Qint, Qah, Ria,
                             pR_ie, pR_ea, pC_in, pC_en,
                             pA_si, pA_se, pA_ii, pA_ie, pTin0, out, n);
        return;
    }

    dim3 pgrid(C / 32, S2 / 32);             // (1024, 4) blocks of 256
    pre_t_kernel<<<pgrid, 256>>>(To, Irr, Qint, Qah, Ria,
                                 pR_ie, pR_ea, pC_in, pC_en,
                                 pA_si, pA_se, pA_ii, pA_ie, C);

    int threads = C / 2;                     // two chains per thread
    scan_t_kernel<<<threads / 128, 128>>>(out, pR_ie, pR_ea, pC_in, pC_en,
                                          pTin0, C);
}

// round 8
// speedup vs baseline: 1.0860x; 1.0054x over previous
#include <cuda_runtime.h>
#include <cuda_fp16.h>

// RC backward-Euler scan. v8:
//  - coefficients 8 B/step: b (fp32) + (h,g) packed __half2, transposed planes
//  - S=128, warm-up = 3 chunks (384 steps) -> same math/accuracy as v7
//  - scan: per-thread cp.async (LDGSTS) smem FIFO, DEPTH=8 stages x 4 steps
//    (32 steps ~ 600+ cyc prefetch: covers 577-cyc DRAM-cold loads with ZERO
//    register cost). No cross-thread smem sharing -> wait_group only, no bar.
//  - 1 chain/thread, 256 blocks x 128 thr (~2 warps/SMSP)

#define DT_S   1800.0f
#define GA     31.388f
#define S2     128
#define PWARM  3
#define NSEG   (PWARM + 1)
#define TOTST  (NSEG * (S2 / 4))     // 128 stages of 4 steps
#define DEPTH  8
#define TPB    128
#define NMAX   (1 << 22)

static __device__ float4 g_b4[NMAX / 4];    // 4 steps of b per entry
static __device__ uint4  g_hg4[NMAX / 4];   // 4 steps of packed (h,g) per entry

struct DCst {
    float iRie, iRea, invCin, invCen;
    float M11, nM12, nM21;
    float kD, kE, k0a, k1a;
    float gam, del, c_h, c_g1, dtCen;
};

__device__ __forceinline__ DCst make_consts(float R_ie, float R_ea,
                                            float C_in, float C_en)
{
    DCst c;
    c.iRie   = 1.0f / R_ie;
    c.iRea   = 1.0f / R_ea;
    c.invCin = 1.0f / C_in;
    c.invCen = 1.0f / C_en;
    c.M11  = 1.0f + DT_S * (c.iRea + c.iRie) * c.invCen;
    c.nM12 = DT_S * c.iRie * c.invCen;
    c.nM21 = DT_S * c.iRie * c.invCin;
    c.kD   = c.M11  / c.nM12;
    c.kE   = c.nM21 / c.nM12;
    c.k0a  = 1.0f / c.M11;
    c.k1a  = c.nM21 / c.M11;
    float alpha = 1.0f + DT_S * c.iRie * c.invCin;   // M22 = alpha + beta*u
    float beta  = DT_S * c.invCin;
    c.gam  = c.M11 * alpha - c.nM12 * c.nM21;        // det = gam + del*u
    c.del  = c.M11 * beta;
    c.c_h  = c.nM12 * DT_S * c.invCin;
    c.c_g1 = c.M11  * DT_S * c.invCin;
    c.dtCen = DT_S * c.invCen;
    return c;
}

__device__ __forceinline__ float frcp_approx(float x) {
    float r;
    asm("rcp.approx.f32 %0, %1;" : "=f"(r) : "f"(x));
    return r;
}

// ------------------------------------------- pre-pass: compute + transpose
__global__ void __launch_bounds__(256)
pre_t_kernel(const float* __restrict__ To,  const float* __restrict__ Irr,
             const float* __restrict__ Qint, const float* __restrict__ Qah,
             const float* __restrict__ Ria,
             const float* pR_ie, const float* pR_ea,
             const float* pC_in, const float* pC_en,
             const float* pA_si, const float* pA_se,
             const float* pA_ii, const float* pA_ie,
             int C)
{
    __shared__ float4 tb[8][33];
    __shared__ uint4  th[8][33];

    const DCst c = make_consts(__ldg(pR_ie), __ldg(pR_ea), __ldg(pC_in), __ldg(pC_en));
    float a_si = __ldg(pA_si), a_se = __ldg(pA_se);
    float a_ii = __ldg(pA_ii), a_ie = __ldg(pA_ie);

    int j0 = blockIdx.x * 32;
    int k0 = blockIdx.y * 32;

    {   // phase 1: coalesced read + compute
        int kg = threadIdx.x & 7;        // 0..7 (x4 steps)
        int jj = threadIdx.x >> 3;       // 0..31
        int t  = (j0 + jj) * S2 + k0 + 4 * kg;

        float4 to4 = *(const float4*)(To  + t);
        float4 ir4 = *(const float4*)(Irr + t);
        float4 qi4 = *(const float4*)(Qint + t);
        float4 qa4 = *(const float4*)(Qah + t);
        float4 ra4 = *(const float4*)(Ria + t);
        const float* to = (const float*)&to4;
        const float* ir = (const float*)&ir4;
        const float* qi = (const float*)&qi4;
        const float* qa = (const float*)&qa4;
        const float* ra = (const float*)&ra4;

        float Rc[4], P[4], ipv[4];
        #pragma unroll
        for (int i = 0; i < 4; ++i) {
            Rc[i] = fmaxf(ra[i], 1e-4f);
            P[i]  = fmaf(c.gam, Rc[i], c.del);
        }
        float p01 = P[0] * P[1], p23 = P[2] * P[3];
        float ipa = frcp_approx(p01 * p23);
        float i01 = ipa * p23, i23 = ipa * p01;
        ipv[0] = i01 * P[1]; ipv[1] = i01 * P[0];
        ipv[2] = i23 * P[3]; ipv[3] = i23 * P[2];
        #pragma unroll
        for (int i = 0; i < 4; ++i)      // one Newton polish
            ipv[i] = ipv[i] * fmaf(-P[i], ipv[i], 2.0f);

        float4 b4;  float* bp = (float*)&b4;
        uint4  hg4; unsigned* hp = (unsigned*)&hg4;
        #pragma unroll
        for (int i = 0; i < 4; ++i) {
            float ip  = ipv[i];
            float rp  = Rc[i] * ip;                 // invdet
            float Qs  = GA * fminf(fmaxf(ir[i], 0.0f), 2000.0f);
            float qh  = fmaxf(qa[i], 0.0f);
            float b   = c.nM12 * rp;
            float a   = fmaf(c.k1a, b, c.k0a);
            float s0  = c.dtCen * fmaf(to[i], c.iRea,
                                 fmaf(a_se, Qs, a_ie * qi[i]));
            float s1  = fmaf(a_si, Qs, fmaf(a_ii, qi[i], qh));
            float T1  = ip * fmaf(Rc[i], s1, to[i]);
            float h   = fmaf(c.c_h, T1, a * s0);
            float g   = fmaf(c.c_g1, T1, c.nM21 * (rp * s0));
            bp[i] = b;
            __half2 p = __floats2half2_rn(h, g);
            hp[i] = *reinterpret_cast<unsigned*>(&p);
        }
        tb[kg][jj] = b4;
        th[kg][jj] = hg4;
    }
    __syncthreads();
    {   // phase 2: transposed coalesced 512B writes
        int jj = threadIdx.x & 31;
        int kg = threadIdx.x >> 5;       // 0..7
        int idx = ((k0 >> 2) + kg) * C + j0 + jj;
        g_b4[idx]  = tb[kg][jj];
        g_hg4[idx] = th[kg][jj];
    }
}

// ------------------------------------------------------------- scan kernel
__device__ __forceinline__ void cpa16(unsigned saddr, const void* gaddr) {
    asm volatile("cp.async.cg.shared.global [%0], [%1], 16;"
                 :: "r"(saddr), "l"(gaddr));
}

__global__ void __launch_bounds__(TPB)
scan_t_kernel(float* __restrict__ out,
              const float* pR_ie, const float* pR_ea,
              const float* pC_in, const float* pC_en,
              const float* pTin0, int C)
{
    __shared__ float4 sb[DEPTH][TPB];
    __shared__ uint4  sh[DEPTH][TPB];

    int tid = threadIdx.x;
    int j = blockIdx.x * TPB + tid;
    if (j >= C) return;

    const DCst c = make_consts(__ldg(pR_ie), __ldg(pR_ea), __ldg(pC_in), __ldg(pC_en));
    float kD = c.kD, kE = c.kE, k0a = c.k0a, k1a = c.k1a;
    float Tin0 = __ldg(pTin0);

    unsigned sb_base = (unsigned)__cvta_generic_to_shared(&sb[0][tid]);
    unsigned sh_base = (unsigned)__cvta_generic_to_shared(&sh[0][tid]);
    int colBase = j - PWARM;

    // prologue: issue first DEPTH-1 stages
    #pragma unroll
    for (int s = 0; s < DEPTH - 1; ++s) {
        int seg = s >> 5;
        int col = colBase + seg; if (col < 0) col = 0;
        int row = s & 31;
        cpa16(sb_base + (unsigned)(s % DEPTH) * (TPB * 16), &g_b4[row * C + col]);
        cpa16(sh_base + (unsigned)(s % DEPTH) * (TPB * 16), &g_hg4[row * C + col]);
        asm volatile("cp.async.commit_group;");
    }

    float Te = Tin0, Tin = Tin0;
    float* outBase = out + j * S2;

    #pragma unroll 1
    for (int s = 0; s < TOTST; ++s) {
        // issue stage s+DEPTH-1 (empty group past the end keeps counts exact)
        int sp = s + DEPTH - 1;
        if (sp < TOTST) {
            int seg = sp >> 5;
            int col = colBase + seg; if (col < 0) col = 0;
            int row = sp & 31;
            unsigned slot = (unsigned)(sp & (DEPTH - 1)) * (TPB * 16);
            cpa16(sb_base + slot, &g_b4[row * C + col]);
            cpa16(sh_base + slot, &g_hg4[row * C + col]);
        }
        asm volatile("cp.async.commit_group;");
        // wait for stage s (DEPTH groups in flight -> keep DEPTH-1 pending)
        asm volatile("cp.async.wait_group %0;" :: "n"(DEPTH - 1));

        int slot = s & (DEPTH - 1);
        float4 b4  = sb[slot][tid];
        uint4  hg4 = sh[slot][tid];
        const float*    bb = (const float*)&b4;
        const unsigned* hh = (const unsigned*)&hg4;

        float4 v; float* vv = (float*)&v;
        #pragma unroll
        for (int e = 0; e < 4; ++e) {
            float b = bb[e];
            unsigned u = hh[e];
            float2 hg = __half22float2(*reinterpret_cast<const __half2*>(&u));
            float a  = fmaf(k1a, b, k0a);
            float dd = kD * b;
            float ee = kE * b;
            float p  = fmaf(b,  Tin, hg.x);
            float q  = fmaf(ee, Te,  hg.y);
            float Te_n  = fmaf(a,  Te,  p);
            float Tin_n = fmaf(dd, Tin, q);
            Tin_n = fminf(fmaxf(Tin_n, 5.0f), 45.0f);
            Te = Te_n; Tin = Tin_n;
            vv[e] = Tin;
        }

        int seg = s >> 5;
        if (seg == PWARM)
            __stcs((float4*)(outBase + (s & 31) * 4), v);
        // end of a warm-up segment that used a clamped (dummy) column:
        // restore the exact initial carry.
        if ((s & 31) == 31 && (colBase + seg) < 0) { Te = Tin0; Tin = Tin0; }
    }
}

// ------------------------------------------- exact fallback (ragged n only)
__global__ void seq_kernel(const float* __restrict__ To, const float* __restrict__ Irr,
                           const float* __restrict__ Qint, const float* __restrict__ Qah,
                           const float* __restrict__ Ria,
                           const float* pR_ie, const float* pR_ea,
                           const float* pC_in, const float* pC_en,
                           const float* pA_si, const float* pA_se,
                           const float* pA_ii, const float* pA_ie,
                           const float* pTin0,
                           float* __restrict__ out, int n)
{
    float iRie = 1.0f / *pR_ie, iRea = 1.0f / *pR_ea;
    float invCin = 1.0f / *pC_in, invCen = 1.0f / *pC_en;
    float a_si = *pA_si, a_se = *pA_se, a_ii = *pA_ii, a_ie = *pA_ie;
    float M11  = 1.0f + DT_S * (iRea + iRie) * invCen;
    float nM12 = DT_S * iRie * invCen;
    float nM21 = DT_S * iRie * invCin;
    float Te = *pTin0, Tin = *pTin0;
    for (int t = 0; t < n; ++t) {
        float Ria_c = fmaxf(Ria[t], 1e-4f);
        float u     = 1.0f / Ria_c;
        float Qsol  = GA * fminf(fmaxf(Irr[t], 0.0f), 2000.0f);
        float qah   = fmaxf(Qah[t], 0.0f);
        float M22 = 1.0f + DT_S * (u + iRie) * invCin;
        float det = M11 * M22 - nM12 * nM21;
        float invdet = 1.0f / det;
        float b0 = To[t] * iRea * invCen + (a_se * Qsol + a_ie * Qint[t]) * invCen;
        float b1 = (To[t] * u + a_si * Qsol + a_ii * Qint[t] + qah) * invCin;
        float r0 = Te + DT_S * b0;
        float r1 = Tin + DT_S * b1;
        float Te_n  = (M22 * r0 + nM12 * r1) * invdet;
        float Tin_n = (M11 * r1 + nM21 * r0) * invdet;
        Tin_n = fminf(fmaxf(Tin_n, 5.0f), 45.0f);
        Te = Te_n; Tin = Tin_n;
        out[t] = Tin_n;
    }
}

extern "C" void kernel_launch(void* const* d_in, const int* in_sizes, int n_in,
                              void* d_out, int out_size)
{
    const float* pR_ie = (const float*)d_in[0];
    const float* pR_ea = (const float*)d_in[1];
    const float* pC_in = (const float*)d_in[2];
    const float* pC_en = (const float*)d_in[3];
    const float* pA_si = (const float*)d_in[4];
    const float* pA_se = (const float*)d_in[5];
    const float* pA_ii = (const float*)d_in[6];
    const float* pA_ie = (const float*)d_in[7];
    const float* pTin0 = (const float*)d_in[8];
    const float* To   = (const float*)d_in[9];
    const float* Irr  = (const float*)d_in[10];
    const float* Qint = (const float*)d_in[11];
    const float* Qah  = (const float*)d_in[12];
    const float* Ria  = (const float*)d_in[13];
    float* out = (float*)d_out;
    int n = in_sizes[9];

    int C = n / S2;
    if (n > NMAX || n <= 0 || (n % S2) != 0 || (C % TPB) != 0) {
        seq_kernel<<<1, 1>>>(To, Irr, Qint, Qah, Ria,
                             pR_ie, pR_ea, pC_in, pC_en,
                             pA_si, pA_se, pA_ii, pA_ie, pTin0, out, n);
        return;
    }

    dim3 pgrid(C / 32, S2 / 32);             // (1024, 4) blocks of 256
    pre_t_kernel<<<pgrid, 256>>>(To, Irr, Qint, Qah, Ria,
                                 pR_ie, pR_ea, pC_in, pC_en,
                                 pA_si, pA_se, pA_ii, pA_ie, C);

    scan_t_kernel<<<C / TPB, TPB>>>(out, pR_ie, pR_ea, pC_in, pC_en, pTin0, C);
}

// round 9
// speedup vs baseline: 1.2469x; 1.1481x over previous
#include <cuda_runtime.h>
#include <cuda_fp16.h>

// RC backward-Euler scan. v9:
//  - coefficients 8 B/step: b (fp32) + (h,g) packed __half2, transposed planes
//  - S=128, warm-up = 2 chunks (256 steps), NSEG=3 passes per thread
//  - scan: per-thread cp.async FIFO (DEPTH=8 stages x 4 steps) with the
//    32-stage segment body FULLY UNROLLED: smem slots, rows, and the
//    prefetch column selection are compile-time -> index ALU eliminated
//  - 1 chain/thread, blocks of 128

#define DT_S   1800.0f
#define GA     31.388f
#define S2     128
#define PWARM  2
#define NSEG   (PWARM + 1)
#define DEPTH  8
#define TPB    128
#define NMAX   (1 << 22)

static __device__ float4 g_b4[NMAX / 4];    // 4 steps of b per entry
static __device__ uint4  g_hg4[NMAX / 4];   // 4 steps of packed (h,g) per entry

struct DCst {
    float iRie, iRea, invCin, invCen;
    float M11, nM12, nM21;
    float kD, kE, k0a, k1a;
    float gam, del, c_h, c_g1, dtCen;
};

__device__ __forceinline__ DCst make_consts(float R_ie, float R_ea,
                                            float C_in, float C_en)
{
    DCst c;
    c.iRie   = 1.0f / R_ie;
    c.iRea   = 1.0f / R_ea;
    c.invCin = 1.0f / C_in;
    c.invCen = 1.0f / C_en;
    c.M11  = 1.0f + DT_S * (c.iRea + c.iRie) * c.invCen;
    c.nM12 = DT_S * c.iRie * c.invCen;
    c.nM21 = DT_S * c.iRie * c.invCin;
    c.kD   = c.M11  / c.nM12;
    c.kE   = c.nM21 / c.nM12;
    c.k0a  = 1.0f / c.M11;
    c.k1a  = c.nM21 / c.M11;
    float alpha = 1.0f + DT_S * c.iRie * c.invCin;   // M22 = alpha + beta*u
    float beta  = DT_S * c.invCin;
    c.gam  = c.M11 * alpha - c.nM12 * c.nM21;        // det = gam + del*u
    c.del  = c.M11 * beta;
    c.c_h  = c.nM12 * DT_S * c.invCin;
    c.c_g1 = c.M11  * DT_S * c.invCin;
    c.dtCen = DT_S * c.invCen;
    return c;
}

__device__ __forceinline__ float frcp_approx(float x) {
    float r;
    asm("rcp.approx.f32 %0, %1;" : "=f"(r) : "f"(x));
    return r;
}

// ------------------------------------------- pre-pass: compute + transpose
__global__ void __launch_bounds__(256)
pre_t_kernel(const float* __restrict__ To,  const float* __restrict__ Irr,
             const float* __restrict__ Qint, const float* __restrict__ Qah,
             const float* __restrict__ Ria,
             const float* pR_ie, const float* pR_ea,
             const float* pC_in, const float* pC_en,
             const float* pA_si, const float* pA_se,
             const float* pA_ii, const float* pA_ie,
             int C)
{
    __shared__ float4 tb[8][33];
    __shared__ uint4  th[8][33];

    const DCst c = make_consts(__ldg(pR_ie), __ldg(pR_ea), __ldg(pC_in), __ldg(pC_en));
    float a_si = __ldg(pA_si), a_se = __ldg(pA_se);
    float a_ii = __ldg(pA_ii), a_ie = __ldg(pA_ie);

    int j0 = blockIdx.x * 32;
    int k0 = blockIdx.y * 32;

    {   // phase 1: coalesced read + compute
        int kg = threadIdx.x & 7;        // 0..7 (x4 steps)
        int jj = threadIdx.x >> 3;       // 0..31
        int t  = (j0 + jj) * S2 + k0 + 4 * kg;

        float4 to4 = *(const float4*)(To  + t);
        float4 ir4 = *(const float4*)(Irr + t);
        float4 qi4 = *(const float4*)(Qint + t);
        float4 qa4 = *(const float4*)(Qah + t);
        float4 ra4 = *(const float4*)(Ria + t);
        const float* to = (const float*)&to4;
        const float* ir = (const float*)&ir4;
        const float* qi = (const float*)&qi4;
        const float* qa = (const float*)&qa4;
        const float* ra = (const float*)&ra4;

        float Rc[4], P[4], ipv[4];
        #pragma unroll
        for (int i = 0; i < 4; ++i) {
            Rc[i] = fmaxf(ra[i], 1e-4f);
            P[i]  = fmaf(c.gam, Rc[i], c.del);
        }
        float p01 = P[0] * P[1], p23 = P[2] * P[3];
        float ipa = frcp_approx(p01 * p23);
        float i01 = ipa * p23, i23 = ipa * p01;
        ipv[0] = i01 * P[1]; ipv[1] = i01 * P[0];
        ipv[2] = i23 * P[3]; ipv[3] = i23 * P[2];
        #pragma unroll
        for (int i = 0; i < 4; ++i)      // one Newton polish
            ipv[i] = ipv[i] * fmaf(-P[i], ipv[i], 2.0f);

        float4 b4;  float* bp = (float*)&b4;
        uint4  hg4; unsigned* hp = (unsigned*)&hg4;
        #pragma unroll
        for (int i = 0; i < 4; ++i) {
            float ip  = ipv[i];
            float rp  = Rc[i] * ip;                 // invdet
            float Qs  = GA * fminf(fmaxf(ir[i], 0.0f), 2000.0f);
            float qh  = fmaxf(qa[i], 0.0f);
            float b   = c.nM12 * rp;
            float a   = fmaf(c.k1a, b, c.k0a);
            float s0  = c.dtCen * fmaf(to[i], c.iRea,
                                 fmaf(a_se, Qs, a_ie * qi[i]));
            float s1  = fmaf(a_si, Qs, fmaf(a_ii, qi[i], qh));
            float T1  = ip * fmaf(Rc[i], s1, to[i]);
            float h   = fmaf(c.c_h, T1, a * s0);
            float g   = fmaf(c.c_g1, T1, c.nM21 * (rp * s0));
            bp[i] = b;
            __half2 p = __floats2half2_rn(h, g);
            hp[i] = *reinterpret_cast<unsigned*>(&p);
        }
        tb[kg][jj] = b4;
        th[kg][jj] = hg4;
    }
    __syncthreads();
    {   // phase 2: transposed coalesced 512B writes
        int jj = threadIdx.x & 31;
        int kg = threadIdx.x >> 5;       // 0..7
        int idx = ((k0 >> 2) + kg) * C + j0 + jj;
        g_b4[idx]  = tb[kg][jj];
        g_hg4[idx] = th[kg][jj];
    }
}

// ------------------------------------------------------------- scan kernel
__device__ __forceinline__ void cpa16(unsigned saddr, const void* gaddr) {
    asm volatile("cp.async.cg.shared.global [%0], [%1], 16;"
                 :: "r"(saddr), "l"(gaddr));
}
#define CP_COMMIT() asm volatile("cp.async.commit_group;")
#define CP_WAIT7()  asm volatile("cp.async.wait_group 7;")

__global__ void __launch_bounds__(TPB)
scan_t_kernel(float* __restrict__ out,
              const float* pR_ie, const float* pR_ea,
              const float* pC_in, const float* pC_en,
              const float* pTin0, int C)
{
    __shared__ float4 sb[DEPTH][TPB];
    __shared__ uint4  sh[DEPTH][TPB];

    int tid = threadIdx.x;
    int j = blockIdx.x * TPB + tid;

    const DCst c = make_consts(__ldg(pR_ie), __ldg(pR_ea), __ldg(pC_in), __ldg(pC_en));
    float kD = c.kD, kE = c.kE, k0a = c.k0a, k1a = c.k1a;
    float Tin0 = __ldg(pTin0);

    unsigned sb_base = (unsigned)__cvta_generic_to_shared(&sb[0][tid]);
    unsigned sh_base = (unsigned)__cvta_generic_to_shared(&sh[0][tid]);
    int colBase = j - PWARM;

    // prologue: stages 0..6 (all in segment 0)
    {
        int col0 = colBase < 0 ? 0 : colBase;
        const float4* pb = g_b4  + col0;
        const uint4*  ph = g_hg4 + col0;
        #pragma unroll
        for (int s = 0; s < DEPTH - 1; ++s) {
            cpa16(sb_base + (unsigned)(s & 7) * (TPB * 16), pb + (size_t)s * C);
            cpa16(sh_base + (unsigned)(s & 7) * (TPB * 16), ph + (size_t)s * C);
            CP_COMMIT();
        }
    }

    float Te = Tin0, Tin = Tin0;
    float* outBase = out + j * S2;

    #pragma unroll 1
    for (int seg = 0; seg < NSEG; ++seg) {
        int colC = colBase + seg;     if (colC < 0) colC = 0;
        int cn   = colBase + seg + 1;
        int colN = cn < 0 ? 0 : (cn > C - 1 ? C - 1 : cn);
        bool doOut = (seg == PWARM);

        const float4* pbC = g_b4  + colC;
        const uint4*  phC = g_hg4 + colC;
        const float4* pbN = g_b4  + colN;
        const uint4*  phN = g_hg4 + colN;

        #pragma unroll
        for (int m = 0; m < 32; ++m) {
            // prefetch stage m+7 (static column/row selection)
            {
                constexpr int prWrap = 1;  (void)prWrap;
                const int pr = m + 7;
                if (pr < 32) {
                    cpa16(sb_base + (unsigned)(pr & 7) * (TPB * 16), pbC + (size_t)pr * C);
                    cpa16(sh_base + (unsigned)(pr & 7) * (TPB * 16), phC + (size_t)pr * C);
                } else {
                    const int r = pr - 32;
                    cpa16(sb_base + (unsigned)(pr & 7) * (TPB * 16), pbN + (size_t)r * C);
                    cpa16(sh_base + (unsigned)(pr & 7) * (TPB * 16), phN + (size_t)r * C);
                }
            }
            CP_COMMIT();
            CP_WAIT7();

            float4 b4  = sb[m & 7][tid];
            uint4  hg4 = sh[m & 7][tid];
            const float*    bb = (const float*)&b4;
            const unsigned* hh = (const unsigned*)&hg4;

            float4 v; float* vv = (float*)&v;
            #pragma unroll
            for (int e = 0; e < 4; ++e) {
                float b = bb[e];
                unsigned u = hh[e];
                float2 hg = __half22float2(*reinterpret_cast<const __half2*>(&u));
                float a  = fmaf(k1a, b, k0a);
                float dd = kD * b;
                float ee = kE * b;
                float p  = fmaf(b,  Tin, hg.x);
                float q  = fmaf(ee, Te,  hg.y);
                float Te_n  = fmaf(a,  Te,  p);
                float Tin_n = fmaf(dd, Tin, q);
                Tin_n = fminf(fmaxf(Tin_n, 5.0f), 45.0f);
                Te = Te_n; Tin = Tin_n;
                vv[e] = Tin;
            }
            if (doOut) __stcs((float4*)(outBase + m * 4), v);
        }

        // segment used a clamped (dummy) column: restore exact initial carry
        if (colBase + seg < 0) { Te = Tin0; Tin = Tin0; }
    }
}

// ------------------------------------------- exact fallback (ragged n only)
__global__ void seq_kernel(const float* __restrict__ To, const float* __restrict__ Irr,
                           const float* __restrict__ Qint, const float* __restrict__ Qah,
                           const float* __restrict__ Ria,
                           const float* pR_ie, const float* pR_ea,
                           const float* pC_in, const float* pC_en,
                           const float* pA_si, const float* pA_se,
                           const float* pA_ii, const float* pA_ie,
                           const float* pTin0,
                           float* __restrict__ out, int n)
{
    float iRie = 1.0f / *pR_ie, iRea = 1.0f / *pR_ea;
    float invCin = 1.0f / *pC_in, invCen = 1.0f / *pC_en;
    float a_si = *pA_si, a_se = *pA_se, a_ii = *pA_ii, a_ie = *pA_ie;
    float M11  = 1.0f + DT_S * (iRea + iRie) * invCen;
    float nM12 = DT_S * iRie * invCen;
    float nM21 = DT_S * iRie * invCin;
    float Te = *pTin0, Tin = *pTin0;
    for (int t = 0; t < n; ++t) {
        float Ria_c = fmaxf(Ria[t], 1e-4f);
        float u     = 1.0f / Ria_c;
        float Qsol  = GA * fminf(fmaxf(Irr[t], 0.0f), 2000.0f);
        float qah   = fmaxf(Qah[t], 0.0f);
        float M22 = 1.0f + DT_S * (u + iRie) * invCin;
        float det = M11 * M22 - nM12 * nM21;
        float invdet = 1.0f / det;
        float b0 = To[t] * iRea * invCen + (a_se * Qsol + a_ie * Qint[t]) * invCen;
        float b1 = (To[t] * u + a_si * Qsol + a_ii * Qint[t] + qah) * invCin;
        float r0 = Te + DT_S * b0;
        float r1 = Tin + DT_S * b1;
        float Te_n  = (M22 * r0 + nM12 * r1) * invdet;
        float Tin_n = (M11 * r1 + nM21 * r0) * invdet;
        Tin_n = fminf(fmaxf(Tin_n, 5.0f), 45.0f);
        Te = Te_n; Tin = Tin_n;
        out[t] = Tin_n;
    }
}

extern "C" void kernel_launch(void* const* d_in, const int* in_sizes, int n_in,
                              void* d_out, int out_size)
{
    const float* pR_ie = (const float*)d_in[0];
    const float* pR_ea = (const float*)d_in[1];
    const float* pC_in = (const float*)d_in[2];
    const float* pC_en = (const float*)d_in[3];
    const float* pA_si = (const float*)d_in[4];
    const float* pA_se = (const float*)d_in[5];
    const float* pA_ii = (const float*)d_in[6];
    const float* pA_ie = (const float*)d_in[7];
    const float* pTin0 = (const float*)d_in[8];
    const float* To   = (const float*)d_in[9];
    const float* Irr  = (const float*)d_in[10];
    const float* Qint = (const float*)d_in[11];
    const float* Qah  = (const float*)d_in[12];
    const float* Ria  = (const float*)d_in[13];
    float* out = (float*)d_out;
    int n = in_sizes[9];

    int C = n / S2;
    if (n > NMAX || n <= 0 || (n % S2) != 0 || (C % TPB) != 0) {
        seq_kernel<<<1, 1>>>(To, Irr, Qint, Qah, Ria,
                             pR_ie, pR_ea, pC_in, pC_en,
                             pA_si, pA_se, pA_ii, pA_ie, pTin0, out, n);
        return;
    }

    dim3 pgrid(C / 32, S2 / 32);             // (1024, 4) blocks of 256
    pre_t_kernel<<<pgrid, 256>>>(To, Irr, Qint, Qah, Ria,
                                 pR_ie, pR_ea, pC_in, pC_en,
                                 pA_si, pA_se, pA_ii, pA_ie, C);

    scan_t_kernel<<<C / TPB, TPB>>>(out, pR_ie, pR_ea, pC_in, pC_en, pTin0, C);
}

// round 10
// speedup vs baseline: 1.2479x; 1.0008x over previous
#include <cuda_runtime.h>
#include <cuda_fp16.h>

// RC backward-Euler scan. v9:
//  - coefficients 8 B/step: b (fp32) + (h,g) packed __half2, transposed planes
//  - S=128, warm-up = 2 chunks (256 steps), NSEG=3 passes per thread
//  - scan: per-thread cp.async FIFO (DEPTH=8 stages x 4 steps) with the
//    32-stage segment body FULLY UNROLLED: smem slots, rows, and the
//    prefetch column selection are compile-time -> index ALU eliminated
//  - 1 chain/thread, blocks of 128

#define DT_S   1800.0f
#define GA     31.388f
#define S2     128
#define PWARM  2
#define NSEG   (PWARM + 1)
#define DEPTH  8
#define TPB    128
#define NMAX   (1 << 22)

static __device__ float4 g_b4[NMAX / 4];    // 4 steps of b per entry
static __device__ uint4  g_hg4[NMAX / 4];   // 4 steps of packed (h,g) per entry

struct DCst {
    float iRie, iRea, invCin, invCen;
    float M11, nM12, nM21;
    float kD, kE, k0a, k1a;
    float gam, del, c_h, c_g1, dtCen;
};

__device__ __forceinline__ DCst make_consts(float R_ie, float R_ea,
                                            float C_in, float C_en)
{
    DCst c;
    c.iRie   = 1.0f / R_ie;
    c.iRea   = 1.0f / R_ea;
    c.invCin = 1.0f / C_in;
    c.invCen = 1.0f / C_en;
    c.M11  = 1.0f + DT_S * (c.iRea + c.iRie) * c.invCen;
    c.nM12 = DT_S * c.iRie * c.invCen;
    c.nM21 = DT_S * c.iRie * c.invCin;
    c.kD   = c.M11  / c.nM12;
    c.kE   = c.nM21 / c.nM12;
    c.k0a  = 1.0f / c.M11;
    c.k1a  = c.nM21 / c.M11;
    float alpha = 1.0f + DT_S * c.iRie * c.invCin;   // M22 = alpha + beta*u
    float beta  = DT_S * c.invCin;
    c.gam  = c.M11 * alpha - c.nM12 * c.nM21;        // det = gam + del*u
    c.del  = c.M11 * beta;
    c.c_h  = c.nM12 * DT_S * c.invCin;
    c.c_g1 = c.M11  * DT_S * c.invCin;
    c.dtCen = DT_S * c.invCen;
    return c;
}

__device__ __forceinline__ float frcp_approx(float x) {
    float r;
    asm("rcp.approx.f32 %0, %1;" : "=f"(r) : "f"(x));
    return r;
}

// ------------------------------------------- pre-pass: compute + transpose
__global__ void __launch_bounds__(256)
pre_t_kernel(const float* __restrict__ To,  const float* __restrict__ Irr,
             const float* __restrict__ Qint, const float* __restrict__ Qah,
             const float* __restrict__ Ria,
             const float* pR_ie, const float* pR_ea,
             const float* pC_in, const float* pC_en,
             const float* pA_si, const float* pA_se,
             const float* pA_ii, const float* pA_ie,
             int C)
{
    __shared__ float4 tb[8][33];
    __shared__ uint4  th[8][33];

    const DCst c = make_consts(__ldg(pR_ie), __ldg(pR_ea), __ldg(pC_in), __ldg(pC_en));
    float a_si = __ldg(pA_si), a_se = __ldg(pA_se);
    float a_ii = __ldg(pA_ii), a_ie = __ldg(pA_ie);

    int j0 = blockIdx.x * 32;
    int k0 = blockIdx.y * 32;

    {   // phase 1: coalesced read + compute
        int kg = threadIdx.x & 7;        // 0..7 (x4 steps)
        int jj = threadIdx.x >> 3;       // 0..31
        int t  = (j0 + jj) * S2 + k0 + 4 * kg;

        float4 to4 = *(const float4*)(To  + t);
        float4 ir4 = *(const float4*)(Irr + t);
        float4 qi4 = *(const float4*)(Qint + t);
        float4 qa4 = *(const float4*)(Qah + t);
        float4 ra4 = *(const float4*)(Ria + t);
        const float* to = (const float*)&to4;
        const float* ir = (const float*)&ir4;
        const float* qi = (const float*)&qi4;
        const float* qa = (const float*)&qa4;
        const float* ra = (const float*)&ra4;

        float Rc[4], P[4], ipv[4];
        #pragma unroll
        for (int i = 0; i < 4; ++i) {
            Rc[i] = fmaxf(ra[i], 1e-4f);
            P[i]  = fmaf(c.gam, Rc[i], c.del);
        }
        float p01 = P[0] * P[1], p23 = P[2] * P[3];
        float ipa = frcp_approx(p01 * p23);
        float i01 = ipa * p23, i23 = ipa * p01;
        ipv[0] = i01 * P[1]; ipv[1] = i01 * P[0];
        ipv[2] = i23 * P[3]; ipv[3] = i23 * P[2];
        #pragma unroll
        for (int i = 0; i < 4; ++i)      // one Newton polish
            ipv[i] = ipv[i] * fmaf(-P[i], ipv[i], 2.0f);

        float4 b4;  float* bp = (float*)&b4;
        uint4  hg4; unsigned* hp = (unsigned*)&hg4;
        #pragma unroll
        for (int i = 0; i < 4; ++i) {
            float ip  = ipv[i];
            float rp  = Rc[i] * ip;                 // invdet
            float Qs  = GA * fminf(fmaxf(ir[i], 0.0f), 2000.0f);
            float qh  = fmaxf(qa[i], 0.0f);
            float b   = c.nM12 * rp;
            float a   = fmaf(c.k1a, b, c.k0a);
            float s0  = c.dtCen * fmaf(to[i], c.iRea,
                                 fmaf(a_se, Qs, a_ie * qi[i]));
            float s1  = fmaf(a_si, Qs, fmaf(a_ii, qi[i], qh));
            float T1  = ip * fmaf(Rc[i], s1, to[i]);
            float h   = fmaf(c.c_h, T1, a * s0);
            float g   = fmaf(c.c_g1, T1, c.nM21 * (rp * s0));
            bp[i] = b;
            __half2 p = __floats2half2_rn(h, g);
            hp[i] = *reinterpret_cast<unsigned*>(&p);
        }
        tb[kg][jj] = b4;
        th[kg][jj] = hg4;
    }
    __syncthreads();
    {   // phase 2: transposed coalesced 512B writes
        int jj = threadIdx.x & 31;
        int kg = threadIdx.x >> 5;       // 0..7
        int idx = ((k0 >> 2) + kg) * C + j0 + jj;
        g_b4[idx]  = tb[kg][jj];
        g_hg4[idx] = th[kg][jj];
    }
}

// ------------------------------------------------------------- scan kernel
__device__ __forceinline__ void cpa16(unsigned saddr, const void* gaddr) {
    asm volatile("cp.async.cg.shared.global [%0], [%1], 16;"
                 :: "r"(saddr), "l"(gaddr));
}
#define CP_COMMIT() asm volatile("cp.async.commit_group;")
#define CP_WAIT7()  asm volatile("cp.async.wait_group 7;")

__global__ void __launch_bounds__(TPB)
scan_t_kernel(float* __restrict__ out,
              const float* pR_ie, const float* pR_ea,
              const float* pC_in, const float* pC_en,
              const float* pTin0, int C)
{
    __shared__ float4 sb[DEPTH][TPB];
    __shared__ uint4  sh[DEPTH][TPB];

    int tid = threadIdx.x;
    int j = blockIdx.x * TPB + tid;

    const DCst c = make_consts(__ldg(pR_ie), __ldg(pR_ea), __ldg(pC_in), __ldg(pC_en));
    float kD = c.kD, kE = c.kE, k0a = c.k0a, k1a = c.k1a;
    float Tin0 = __ldg(pTin0);

    unsigned sb_base = (unsigned)__cvta_generic_to_shared(&sb[0][tid]);
    unsigned sh_base = (unsigned)__cvta_generic_to_shared(&sh[0][tid]);
    int colBase = j - PWARM;

    // prologue: stages 0..6 (all in segment 0)
    {
        int col0 = colBase < 0 ? 0 : colBase;
        const float4* pb = g_b4  + col0;
        const uint4*  ph = g_hg4 + col0;
        #pragma unroll
        for (int s = 0; s < DEPTH - 1; ++s) {
            cpa16(sb_base + (unsigned)(s & 7) * (TPB * 16), pb + (size_t)s * C);
            cpa16(sh_base + (unsigned)(s & 7) * (TPB * 16), ph + (size_t)s * C);
            CP_COMMIT();
        }
    }

    float Te = Tin0, Tin = Tin0;
    float* outBase = out + j * S2;

    #pragma unroll 1
    for (int seg = 0; seg < NSEG; ++seg) {
        int colC = colBase + seg;     if (colC < 0) colC = 0;
        int cn   = colBase + seg + 1;
        int colN = cn < 0 ? 0 : (cn > C - 1 ? C - 1 : cn);
        bool doOut = (seg == PWARM);

        const float4* pbC = g_b4  + colC;
        const uint4*  phC = g_hg4 + colC;
        const float4* pbN = g_b4  + colN;
        const uint4*  phN = g_hg4 + colN;

        #pragma unroll
        for (int m = 0; m < 32; ++m) {
            // prefetch stage m+7 (static column/row selection)
            {
                constexpr int prWrap = 1;  (void)prWrap;
                const int pr = m + 7;
                if (pr < 32) {
                    cpa16(sb_base + (unsigned)(pr & 7) * (TPB * 16), pbC + (size_t)pr * C);
                    cpa16(sh_base + (unsigned)(pr & 7) * (TPB * 16), phC + (size_t)pr * C);
                } else {
                    const int r = pr - 32;
                    cpa16(sb_base + (unsigned)(pr & 7) * (TPB * 16), pbN + (size_t)r * C);
                    cpa16(sh_base + (unsigned)(pr & 7) * (TPB * 16), phN + (size_t)r * C);
                }
            }
            CP_COMMIT();
            CP_WAIT7();

            float4 b4  = sb[m & 7][tid];
            uint4  hg4 = sh[m & 7][tid];
            const float*    bb = (const float*)&b4;
            const unsigned* hh = (const unsigned*)&hg4;

            float4 v; float* vv = (float*)&v;
            #pragma unroll
            for (int e = 0; e < 4; ++e) {
                float b = bb[e];
                unsigned u = hh[e];
                float2 hg = __half22float2(*reinterpret_cast<const __half2*>(&u));
                float a  = fmaf(k1a, b, k0a);
                float dd = kD * b;
                float ee = kE * b;
                float p  = fmaf(b,  Tin, hg.x);
                float q  = fmaf(ee, Te,  hg.y);
                float Te_n  = fmaf(a,  Te,  p);
                float Tin_n = fmaf(dd, Tin, q);
                Tin_n = fminf(fmaxf(Tin_n, 5.0f), 45.0f);
                Te = Te_n; Tin = Tin_n;
                vv[e] = Tin;
            }
            if (doOut) __stcs((float4*)(outBase + m * 4), v);
        }

        // segment used a clamped (dummy) column: restore exact initial carry
        if (colBase + seg < 0) { Te = Tin0; Tin = Tin0; }
    }
}

// ------------------------------------------- exact fallback (ragged n only)
__global__ void seq_kernel(const float* __restrict__ To, const float* __restrict__ Irr,
                           const float* __restrict__ Qint, const float* __restrict__ Qah,
                           const float* __restrict__ Ria,
                           const float* pR_ie, const float* pR_ea,
                           const float* pC_in, const float* pC_en,
                           const float* pA_si, const float* pA_se,
                           const float* pA_ii, const float* pA_ie,
                           const float* pTin0,
                           float* __restrict__ out, int n)
{
    float iRie = 1.0f / *pR_ie, iRea = 1.0f / *pR_ea;
    float invCin = 1.0f / *pC_in, invCen = 1.0f / *pC_en;
    float a_si = *pA_si, a_se = *pA_se, a_ii = *pA_ii, a_ie = *pA_ie;
    float M11  = 1.0f + DT_S * (iRea + iRie) * invCen;
    float nM12 = DT_S * iRie * invCen;
    float nM21 = DT_S * iRie * invCin;
    float Te = *pTin0, Tin = *pTin0;
    for (int t = 0; t < n; ++t) {
        float Ria_c = fmaxf(Ria[t], 1e-4f);
        float u     = 1.0f / Ria_c;
        float Qsol  = GA * fminf(fmaxf(Irr[t], 0.0f), 2000.0f);
        float qah   = fmaxf(Qah[t], 0.0f);
        float M22 = 1.0f + DT_S * (u + iRie) * invCin;
        float det = M11 * M22 - nM12 * nM21;
        float invdet = 1.0f / det;
        float b0 = To[t] * iRea * invCen + (a_se * Qsol + a_ie * Qint[t]) * invCen;
        float b1 = (To[t] * u + a_si * Qsol + a_ii * Qint[t] + qah) * invCin;
        float r0 = Te + DT_S * b0;
        float r1 = Tin + DT_S * b1;
        float Te_n  = (M22 * r0 + nM12 * r1) * invdet;
        float Tin_n = (M11 * r1 + nM21 * r0) * invdet;
        Tin_n = fminf(fmaxf(Tin_n, 5.0f), 45.0f);
        Te = Te_n; Tin = Tin_n;
        out[t] = Tin_n;
    }
}

extern "C" void kernel_launch(void* const* d_in, const int* in_sizes, int n_in,
                              void* d_out, int out_size)
{
    const float* pR_ie = (const float*)d_in[0];
    const float* pR_ea = (const float*)d_in[1];
    const float* pC_in = (const float*)d_in[2];
    const float* pC_en = (const float*)d_in[3];
    const float* pA_si = (const float*)d_in[4];
    const float* pA_se = (const float*)d_in[5];
    const float* pA_ii = (const float*)d_in[6];
    const float* pA_ie = (const float*)d_in[7];
    const float* pTin0 = (const float*)d_in[8];
    const float* To   = (const float*)d_in[9];
    const float* Irr  = (const float*)d_in[10];
    const float* Qint = (const float*)d_in[11];
    const float* Qah  = (const float*)d_in[12];
    const float* Ria  = (const float*)d_in[13];
    float* out = (float*)d_out;
    int n = in_sizes[9];

    int C = n / S2;
    if (n > NMAX || n <= 0 || (n % S2) != 0 || (C % TPB) != 0) {
        seq_kernel<<<1, 1>>>(To, Irr, Qint, Qah, Ria,
                             pR_ie, pR_ea, pC_in, pC_en,
                             pA_si, pA_se, pA_ii, pA_ie, pTin0, out, n);
        return;
    }

    dim3 pgrid(C / 32, S2 / 32);             // (1024, 4) blocks of 256
    pre_t_kernel<<<pgrid, 256>>>(To, Irr, Qint, Qah, Ria,
                                 pR_ie, pR_ea, pC_in, pC_en,
                                 pA_si, pA_se, pA_ii, pA_ie, C);

    scan_t_kernel<<<C / TPB, TPB>>>(out, pR_ie, pR_ea, pC_in, pC_en, pTin0, C);
}